// round 7
// baseline (speedup 1.0000x reference)
#include <cuda_runtime.h>
#include <cuda_bf16.h>
#include <cstdint>
#include <cstddef>

// Problem constants
#define BSZ   4
#define TLEN  2048
#define CDIM  1024
#define NH    16
#define DH    64
#define MROWS (BSZ * TLEN)          // 8192
#define THREEC (3 * CDIM)           // 3072

// ---------------------------------------------------------------------------
// Scratch device globals
// ---------------------------------------------------------------------------
__device__ __nv_bfloat16 g_x_hi[(size_t)MROWS * CDIM];
__device__ __nv_bfloat16 g_x_lo[(size_t)MROWS * CDIM];
__device__ __nv_bfloat16 g_wqkv_hi[(size_t)THREEC * CDIM]; // W_qkv^T [N,K]
__device__ __nv_bfloat16 g_wqkv_lo[(size_t)THREEC * CDIM];
__device__ __nv_bfloat16 g_wp_hi[(size_t)CDIM * CDIM];     // W_proj^T [N,K]
__device__ __nv_bfloat16 g_wp_lo[(size_t)CDIM * CDIM];
// q,k: [b][h][t][d]; v transposed: [b][h][d][t]
__device__ __nv_bfloat16 g_qh[(size_t)MROWS * CDIM];
__device__ __nv_bfloat16 g_ql[(size_t)MROWS * CDIM];
__device__ __nv_bfloat16 g_kh[(size_t)MROWS * CDIM];
__device__ __nv_bfloat16 g_kl[(size_t)MROWS * CDIM];
__device__ __nv_bfloat16 g_vth[(size_t)MROWS * CDIM];
__device__ __nv_bfloat16 g_vtl[(size_t)MROWS * CDIM];
__device__ __nv_bfloat16 g_attn_hi[(size_t)MROWS * CDIM];  // [b*T+t][h*64+d]
__device__ __nv_bfloat16 g_attn_lo[(size_t)MROWS * CDIM];

// ---------------------------------------------------------------------------
// Helpers
// ---------------------------------------------------------------------------
__device__ __forceinline__ uint32_t smem_u32(const void* p) {
    uint32_t a;
    asm("{ .reg .u64 t; cvta.to.shared.u64 t, %1; cvt.u32.u64 %0, t; }"
        : "=r"(a) : "l"(p));
    return a;
}

__device__ __forceinline__ void cp_async16(uint32_t saddr, const void* gaddr) {
    asm volatile("cp.async.cg.shared.global [%0], [%1], 16;"
                 :: "r"(saddr), "l"(gaddr) : "memory");
}
#define CP_COMMIT() asm volatile("cp.async.commit_group;" ::: "memory")
#define CP_WAIT(n)  asm volatile("cp.async.wait_group %0;" :: "n"(n) : "memory")

__device__ __forceinline__ void mma_bf16(float* d, const uint32_t* a,
                                         uint32_t b0, uint32_t b1) {
    asm volatile(
        "mma.sync.aligned.m16n8k16.row.col.f32.bf16.bf16.f32 "
        "{%0,%1,%2,%3}, {%4,%5,%6,%7}, {%8,%9}, {%0,%1,%2,%3};"
        : "+f"(d[0]), "+f"(d[1]), "+f"(d[2]), "+f"(d[3])
        : "r"(a[0]), "r"(a[1]), "r"(a[2]), "r"(a[3]), "r"(b0), "r"(b1));
}

__device__ __forceinline__ void ldsm_x4(uint32_t* r, uint32_t addr) {
    asm volatile("ldmatrix.sync.aligned.m8n8.x4.shared.b16 {%0,%1,%2,%3}, [%4];"
                 : "=r"(r[0]), "=r"(r[1]), "=r"(r[2]), "=r"(r[3]) : "r"(addr));
}

// split two fp32 into packed bf16x2 hi and lo words
__device__ __forceinline__ void split2(float a, float b, uint32_t& hi, uint32_t& lo) {
    __nv_bfloat16 ha = __float2bfloat16(a), hb = __float2bfloat16(b);
    __nv_bfloat16 la = __float2bfloat16(a - __bfloat162float(ha));
    __nv_bfloat16 lb = __float2bfloat16(b - __bfloat162float(hb));
    hi = (uint32_t)__bfloat16_as_ushort(ha) | ((uint32_t)__bfloat16_as_ushort(hb) << 16);
    lo = (uint32_t)__bfloat16_as_ushort(la) | ((uint32_t)__bfloat16_as_ushort(lb) << 16);
}

// ---------------------------------------------------------------------------
// Prep kernels
// ---------------------------------------------------------------------------
__global__ void split_kernel(const float4* __restrict__ in,
                             uint2* __restrict__ hi, uint2* __restrict__ lo, int n4)
{
    for (int i = blockIdx.x * blockDim.x + threadIdx.x; i < n4; i += gridDim.x * blockDim.x) {
        float4 v = in[i];
        uint2 H, L;
        split2(v.x, v.y, H.x, L.x);
        split2(v.z, v.w, H.y, L.y);
        hi[i] = H;
        lo[i] = L;
    }
}

__global__ void transpose_split_kernel(const float* __restrict__ W,
                                       __nv_bfloat16* __restrict__ hi,
                                       __nv_bfloat16* __restrict__ lo,
                                       int K, int N)
{
    __shared__ float t[32][33];
    int n = blockIdx.x * 32 + threadIdx.x;
    int k = blockIdx.y * 32 + threadIdx.y;
    #pragma unroll
    for (int j = 0; j < 4; j++)
        t[threadIdx.y + j * 8][threadIdx.x] = W[(size_t)(k + j * 8) * N + n];
    __syncthreads();
    int k2 = blockIdx.y * 32 + threadIdx.x;
    int n2 = blockIdx.x * 32 + threadIdx.y;
    #pragma unroll
    for (int j = 0; j < 4; j++) {
        float v = t[threadIdx.x][threadIdx.y + j * 8];
        __nv_bfloat16 h = __float2bfloat16(v);
        hi[(size_t)(n2 + j * 8) * K + k2] = h;
        lo[(size_t)(n2 + j * 8) * K + k2] = __float2bfloat16(v - __bfloat162float(h));
    }
}

// ---------------------------------------------------------------------------
// mma.sync bf16x3 GEMM: C = (Ahi+Alo) @ (Bhi+Blo)^T + bias
// 256x128x32 CTA tile, 256 threads (8 warps, 4m x 2n), warp tile 64x64.
// MODE 0: fp32 store to C.   MODE 1: QKV epilogue (split + head remap).
// ---------------------------------------------------------------------------
#define PAD    40
#define A_TB   (256 * PAD * 2)            // 20480
#define B_TB   (128 * PAD * 2)            // 10240
#define STAGE  (2 * A_TB + 2 * B_TB)      // 61440
#define GSMEM  (2 * STAGE)                // 122880

template<int MODE>
__global__ __launch_bounds__(256) void gemm_mma_kernel(
    const __nv_bfloat16* __restrict__ Ahi,
    const __nv_bfloat16* __restrict__ Alo,
    const __nv_bfloat16* __restrict__ Bhi,
    const __nv_bfloat16* __restrict__ Blo,
    const float* __restrict__ bias,
    float* __restrict__ C,
    int M, int N, int K)
{
    extern __shared__ __align__(128) char smem[];
    const int tid  = threadIdx.x;
    const int wid  = tid >> 5;
    const int lane = tid & 31;
    const int wm   = wid & 3;            // 0..3
    const int wn   = wid >> 2;           // 0..1
    const int lr8  = lane & 7;
    const int g    = lane >> 3;
    const uint32_t sbase = smem_u32(smem);

    const int row0 = blockIdx.y * 256;
    const int col0 = blockIdx.x * 128;
    const int S = K >> 5;

    float acc[4][8][4] = {};

    const int lr  = tid >> 2;            // 0..63
    const int lc8 = (tid & 3) * 8;
    auto load_stage = [&](int s) {
        const uint32_t sb = sbase + (s & 1) * STAGE;
        const int k0 = s * 32;
        #pragma unroll
        for (int i = 0; i < 4; i++) {
            int r = lr + i * 64;
            uint32_t so = sb + (uint32_t)(r * (PAD * 2) + lc8 * 2);
            size_t ga = (size_t)(row0 + r) * K + k0 + lc8;
            cp_async16(so,        Ahi + ga);
            cp_async16(so + A_TB, Alo + ga);
        }
        #pragma unroll
        for (int i = 0; i < 2; i++) {
            int r = lr + i * 64;
            uint32_t so = sb + 2 * A_TB + (uint32_t)(r * (PAD * 2) + lc8 * 2);
            size_t gb = (size_t)(col0 + r) * K + k0 + lc8;
            cp_async16(so,        Bhi + gb);
            cp_async16(so + B_TB, Blo + gb);
        }
        CP_COMMIT();
    };

    load_stage(0);

    for (int s = 0; s < S; s++) {
        if (s + 1 < S) { load_stage(s + 1); CP_WAIT(1); } else { CP_WAIT(0); }
        __syncthreads();

        const uint32_t sA = sbase + (s & 1) * STAGE;
        const uint32_t sB = sA + 2 * A_TB;

        #pragma unroll
        for (int kk = 0; kk < 2; kk++) {
            uint32_t ahi[4][4], alo[4][4], bhi[8][2], blo[8][2];
            #pragma unroll
            for (int mt = 0; mt < 4; mt++) {
                uint32_t a = sA + (uint32_t)(((wm * 64 + mt * 16 + (g & 1) * 8 + lr8) * PAD
                                              + kk * 16 + (g >> 1) * 8) * 2);
                ldsm_x4(ahi[mt], a);
                ldsm_x4(alo[mt], a + A_TB);
            }
            #pragma unroll
            for (int np = 0; np < 4; np++) {
                uint32_t a = sB + (uint32_t)(((wn * 64 + np * 16 + (g >> 1) * 8 + lr8) * PAD
                                              + kk * 16 + (g & 1) * 8) * 2);
                uint32_t th[4], tl[4];
                ldsm_x4(th, a);
                ldsm_x4(tl, a + B_TB);
                bhi[2 * np][0] = th[0]; bhi[2 * np][1] = th[1];
                bhi[2 * np + 1][0] = th[2]; bhi[2 * np + 1][1] = th[3];
                blo[2 * np][0] = tl[0]; blo[2 * np][1] = tl[1];
                blo[2 * np + 1][0] = tl[2]; blo[2 * np + 1][1] = tl[3];
            }
            #pragma unroll
            for (int mt = 0; mt < 4; mt++)
                #pragma unroll
                for (int nt = 0; nt < 8; nt++) {
                    mma_bf16(acc[mt][nt], ahi[mt], bhi[nt][0], bhi[nt][1]);
                    mma_bf16(acc[mt][nt], ahi[mt], blo[nt][0], blo[nt][1]);
                    mma_bf16(acc[mt][nt], alo[mt], bhi[nt][0], bhi[nt][1]);
                }
        }
        __syncthreads();
    }

    // ---- epilogue ----
    #pragma unroll
    for (int mt = 0; mt < 4; mt++) {
        #pragma unroll
        for (int nt = 0; nt < 8; nt++) {
            int r = row0 + wm * 64 + mt * 16 + (lane >> 2);
            int c = col0 + wn * 64 + nt * 8 + (lane & 3) * 2;
            float2 bv = *(const float2*)(bias + c);
            float v00 = acc[mt][nt][0] + bv.x, v01 = acc[mt][nt][1] + bv.y;
            float v10 = acc[mt][nt][2] + bv.x, v11 = acc[mt][nt][3] + bv.y;
            if (MODE == 0) {
                *(float2*)(C + (size_t)r * N + c)       = make_float2(v00, v01);
                *(float2*)(C + (size_t)(r + 8) * N + c) = make_float2(v10, v11);
            } else {
                const int sect = c >> 10;
                const int h = (c & 1023) >> 6;
                const int d = c & 63;
                #pragma unroll
                for (int half = 0; half < 2; half++) {
                    int rr = r + half * 8;
                    float a = half ? v10 : v00;
                    float bb = half ? v11 : v01;
                    int bidx = rr >> 11, t = rr & 2047;
                    if (sect == 0) { a *= 0.125f; bb *= 0.125f; }
                    uint32_t hiw, low;
                    if (sect == 2) {
                        __nv_bfloat16 ha = __float2bfloat16(a), hb = __float2bfloat16(bb);
                        __nv_bfloat16 la = __float2bfloat16(a - __bfloat162float(ha));
                        __nv_bfloat16 lb = __float2bfloat16(bb - __bfloat162float(hb));
                        size_t vb = ((size_t)(bidx * NH + h) * 64 + d) * TLEN + t;
                        g_vth[vb] = ha; g_vth[vb + TLEN] = hb;
                        g_vtl[vb] = la; g_vtl[vb + TLEN] = lb;
                    } else {
                        split2(a, bb, hiw, low);
                        size_t qb = ((size_t)(bidx * NH + h) * TLEN + t) * 64 + d;
                        if (sect == 0) {
                            *(uint32_t*)(g_qh + qb) = hiw;
                            *(uint32_t*)(g_ql + qb) = low;
                        } else {
                            *(uint32_t*)(g_kh + qb) = hiw;
                            *(uint32_t*)(g_kl + qb) = low;
                        }
                    }
                }
            }
        }
    }
}

// ---------------------------------------------------------------------------
// Flash attention, mma.sync bf16x3 + ldmatrix. 128 queries/CTA, 4 warps
// (32 q rows each), 64-key stages. grid (T/128, H, B), block 128.
// ---------------------------------------------------------------------------
#define AST   72                      // bf16 elems per smem row (144B)
#define ATILE (64 * AST * 2)          // 9216 B
#define ASTAGE (4 * ATILE)            // 36864 B
#define ASMEM  (2 * ASTAGE)           // 73728 B

__global__ __launch_bounds__(128) void attn_mma_kernel()
{
    extern __shared__ __align__(128) char smem[];
    const int tid  = threadIdx.x;
    const int wid  = tid >> 5;        // 0..3
    const int lane = tid & 31;
    const int lr8  = lane & 7;
    const int g    = lane >> 3;
    const uint32_t sbase = smem_u32(smem);

    const int qt = (int)(gridDim.x - 1) - (int)blockIdx.x;   // reversed
    const size_t bh = (size_t)blockIdx.z * NH + blockIdx.y;

    // ---- stage Q tile (128 rows, hi/lo) into buffer 0, extract fragments ----
    {
        #pragma unroll
        for (int i = 0; i < 8; i++) {
            int f = i * 128 + tid;            // 0..1023
            int r = f >> 3, ch = f & 7;
            uint32_t so = sbase + (uint32_t)(r * 144 + ch * 16);
            size_t ga = ((bh * TLEN + qt * 128 + r) << 6) + ch * 8;
            cp_async16(so,         g_qh + ga);
            cp_async16(so + 18432, g_ql + ga);
        }
        CP_COMMIT();
        CP_WAIT(0);
        __syncthreads();
    }

    uint32_t qhi[2][4][4], qlo[2][4][4];
    #pragma unroll
    for (int mt = 0; mt < 2; mt++)
        #pragma unroll
        for (int ks = 0; ks < 4; ks++) {
            uint32_t a = sbase + (uint32_t)(((wid * 32 + mt * 16 + (g & 1) * 8 + lr8) * AST
                                             + ks * 16 + (g >> 1) * 8) * 2);
            ldsm_x4(qhi[mt][ks], a);
            ldsm_x4(qlo[mt][ks], a + 18432);
        }
    __syncthreads();   // done reading buffer 0 as Q

    float o[2][8][4] = {};
    float m[2][2] = {{-1e30f, -1e30f}, {-1e30f, -1e30f}};
    float l[2][2] = {};

    auto load_kv = [&](int kt) {
        const uint32_t sb = sbase + (kt & 1) * ASTAGE;
        #pragma unroll
        for (int i = 0; i < 4; i++) {
            int f = i * 128 + tid;
            int r = f >> 3, ch = f & 7;
            uint32_t so = sb + (uint32_t)(r * 144 + ch * 16);
            size_t gk = ((bh * TLEN + kt * 64 + r) << 6) + ch * 8;
            size_t gv = (bh * 64 + r) * TLEN + kt * 64 + ch * 8;
            cp_async16(so + 0 * ATILE, g_kh + gk);
            cp_async16(so + 1 * ATILE, g_kl + gk);
            cp_async16(so + 2 * ATILE, g_vth + gv);
            cp_async16(so + 3 * ATILE, g_vtl + gv);
        }
        CP_COMMIT();
    };

    const int nkt = 2 * qt + 2;
    load_kv(0);

    for (int kt = 0; kt < nkt; kt++) {
        if (kt + 1 < nkt) { load_kv(kt + 1); CP_WAIT(1); } else { CP_WAIT(0); }
        __syncthreads();

        const uint32_t sbK = sbase + (kt & 1) * ASTAGE;
        const uint32_t sbV = sbK + 2 * ATILE;

        // ---- S = Q K^T ----
        float s[2][8][4] = {};
        #pragma unroll
        for (int ks = 0; ks < 4; ks++) {
            #pragma unroll
            for (int np = 0; np < 4; np++) {
                uint32_t a = sbK + (uint32_t)(((np * 16 + (g >> 1) * 8 + lr8) * AST
                                               + ks * 16 + (g & 1) * 8) * 2);
                uint32_t kh4[4], kl4[4];
                ldsm_x4(kh4, a);
                ldsm_x4(kl4, a + ATILE);
                #pragma unroll
                for (int mt = 0; mt < 2; mt++) {
                    mma_bf16(s[mt][2 * np],     qhi[mt][ks], kh4[0], kh4[1]);
                    mma_bf16(s[mt][2 * np],     qhi[mt][ks], kl4[0], kl4[1]);
                    mma_bf16(s[mt][2 * np],     qlo[mt][ks], kh4[0], kh4[1]);
                    mma_bf16(s[mt][2 * np + 1], qhi[mt][ks], kh4[2], kh4[3]);
                    mma_bf16(s[mt][2 * np + 1], qhi[mt][ks], kl4[2], kl4[3]);
                    mma_bf16(s[mt][2 * np + 1], qlo[mt][ks], kh4[2], kh4[3]);
                }
            }
        }

        // ---- causal mask on diagonal tiles ----
        if (kt >= 2 * qt) {
            #pragma unroll
            for (int mt = 0; mt < 2; mt++) {
                int qr = qt * 128 + wid * 32 + mt * 16 + (lane >> 2);
                #pragma unroll
                for (int nt = 0; nt < 8; nt++) {
                    int kc = kt * 64 + nt * 8 + (lane & 3) * 2;
                    if (kc > qr)         s[mt][nt][0] = -1e30f;
                    if (kc + 1 > qr)     s[mt][nt][1] = -1e30f;
                    if (kc > qr + 8)     s[mt][nt][2] = -1e30f;
                    if (kc + 1 > qr + 8) s[mt][nt][3] = -1e30f;
                }
            }
        }

        // ---- online softmax + P pack + O += P V ----
        #pragma unroll
        for (int mt = 0; mt < 2; mt++) {
            float mx0 = -1e30f, mx1 = -1e30f;
            #pragma unroll
            for (int nt = 0; nt < 8; nt++) {
                mx0 = fmaxf(mx0, fmaxf(s[mt][nt][0], s[mt][nt][1]));
                mx1 = fmaxf(mx1, fmaxf(s[mt][nt][2], s[mt][nt][3]));
            }
            mx0 = fmaxf(mx0, __shfl_xor_sync(0xffffffff, mx0, 1));
            mx0 = fmaxf(mx0, __shfl_xor_sync(0xffffffff, mx0, 2));
            mx1 = fmaxf(mx1, __shfl_xor_sync(0xffffffff, mx1, 1));
            mx1 = fmaxf(mx1, __shfl_xor_sync(0xffffffff, mx1, 2));

            float mn0 = fmaxf(m[mt][0], mx0), mn1 = fmaxf(m[mt][1], mx1);
            float a0 = __expf(m[mt][0] - mn0), a1 = __expf(m[mt][1] - mn1);
            m[mt][0] = mn0; m[mt][1] = mn1;
            #pragma unroll
            for (int nt = 0; nt < 8; nt++) {
                o[mt][nt][0] *= a0; o[mt][nt][1] *= a0;
                o[mt][nt][2] *= a1; o[mt][nt][3] *= a1;
            }

            float sum0 = 0.f, sum1 = 0.f;
            #pragma unroll
            for (int nt = 0; nt < 8; nt++) {
                s[mt][nt][0] = __expf(s[mt][nt][0] - mn0);
                s[mt][nt][1] = __expf(s[mt][nt][1] - mn0);
                s[mt][nt][2] = __expf(s[mt][nt][2] - mn1);
                s[mt][nt][3] = __expf(s[mt][nt][3] - mn1);
                sum0 += s[mt][nt][0] + s[mt][nt][1];
                sum1 += s[mt][nt][2] + s[mt][nt][3];
            }
            sum0 += __shfl_xor_sync(0xffffffff, sum0, 1);
            sum0 += __shfl_xor_sync(0xffffffff, sum0, 2);
            sum1 += __shfl_xor_sync(0xffffffff, sum1, 1);
            sum1 += __shfl_xor_sync(0xffffffff, sum1, 2);
            l[mt][0] = l[mt][0] * a0 + sum0;
            l[mt][1] = l[mt][1] * a1 + sum1;
        }

        uint32_t phi[2][4][4], plo[2][4][4];
        #pragma unroll
        for (int mt = 0; mt < 2; mt++)
            #pragma unroll
            for (int ks = 0; ks < 4; ks++) {
                split2(s[mt][2 * ks][0],     s[mt][2 * ks][1],     phi[mt][ks][0], plo[mt][ks][0]);
                split2(s[mt][2 * ks][2],     s[mt][2 * ks][3],     phi[mt][ks][1], plo[mt][ks][1]);
                split2(s[mt][2 * ks + 1][0], s[mt][2 * ks + 1][1], phi[mt][ks][2], plo[mt][ks][2]);
                split2(s[mt][2 * ks + 1][2], s[mt][2 * ks + 1][3], phi[mt][ks][3], plo[mt][ks][3]);
            }

        #pragma unroll
        for (int ks = 0; ks < 4; ks++) {
            #pragma unroll
            for (int np = 0; np < 4; np++) {
                uint32_t a = sbV + (uint32_t)(((np * 16 + (g >> 1) * 8 + lr8) * AST
                                               + ks * 16 + (g & 1) * 8) * 2);
                uint32_t vh4[4], vl4[4];
                ldsm_x4(vh4, a);
                ldsm_x4(vl4, a + ATILE);
                #pragma unroll
                for (int mt = 0; mt < 2; mt++) {
                    mma_bf16(o[mt][2 * np],     phi[mt][ks], vh4[0], vh4[1]);
                    mma_bf16(o[mt][2 * np],     plo[mt][ks], vh4[0], vh4[1]);
                    mma_bf16(o[mt][2 * np],     phi[mt][ks], vl4[0], vl4[1]);
                    mma_bf16(o[mt][2 * np + 1], phi[mt][ks], vh4[2], vh4[3]);
                    mma_bf16(o[mt][2 * np + 1], plo[mt][ks], vh4[2], vh4[3]);
                    mma_bf16(o[mt][2 * np + 1], phi[mt][ks], vl4[2], vl4[3]);
                }
            }
        }
        __syncthreads();
    }

    // ---- finalize + store hi/lo split ----
    #pragma unroll
    for (int mt = 0; mt < 2; mt++) {
        const float inv0 = 1.0f / l[mt][0];
        const float inv1 = 1.0f / l[mt][1];
        const int t0 = qt * 128 + wid * 32 + mt * 16 + (lane >> 2);
        const size_t row0 = (size_t)blockIdx.z * TLEN + t0;
        const int colb = blockIdx.y * 64 + (lane & 3) * 2;
        #pragma unroll
        for (int dn = 0; dn < 8; dn++) {
            int col = colb + dn * 8;
            uint32_t hiw, low;
            split2(o[mt][dn][0] * inv0, o[mt][dn][1] * inv0, hiw, low);
            *(uint32_t*)(g_attn_hi + row0 * CDIM + col) = hiw;
            *(uint32_t*)(g_attn_lo + row0 * CDIM + col) = low;
            split2(o[mt][dn][2] * inv1, o[mt][dn][3] * inv1, hiw, low);
            *(uint32_t*)(g_attn_hi + (row0 + 8) * CDIM + col) = hiw;
            *(uint32_t*)(g_attn_lo + (row0 + 8) * CDIM + col) = low;
        }
    }
}

// ---------------------------------------------------------------------------
// kernel_launch
// ---------------------------------------------------------------------------
extern "C" void kernel_launch(void* const* d_in, const int* in_sizes, int n_in,
                              void* d_out, int out_size)
{
    const float* x     = (const float*)d_in[0];
    const float* Wqkv  = (const float*)d_in[1];
    const float* bqkv  = (const float*)d_in[2];
    const float* Wproj = (const float*)d_in[3];
    const float* bproj = (const float*)d_in[4];
    float* out = (float*)d_out;

    __nv_bfloat16 *xh, *xl, *wqh, *wql, *wph, *wpl, *ah, *al;
    cudaGetSymbolAddress((void**)&xh, g_x_hi);
    cudaGetSymbolAddress((void**)&xl, g_x_lo);
    cudaGetSymbolAddress((void**)&wqh, g_wqkv_hi);
    cudaGetSymbolAddress((void**)&wql, g_wqkv_lo);
    cudaGetSymbolAddress((void**)&wph, g_wp_hi);
    cudaGetSymbolAddress((void**)&wpl, g_wp_lo);
    cudaGetSymbolAddress((void**)&ah, g_attn_hi);
    cudaGetSymbolAddress((void**)&al, g_attn_lo);

    cudaFuncSetAttribute(gemm_mma_kernel<0>,
                         cudaFuncAttributeMaxDynamicSharedMemorySize, GSMEM);
    cudaFuncSetAttribute(gemm_mma_kernel<1>,
                         cudaFuncAttributeMaxDynamicSharedMemorySize, GSMEM);
    cudaFuncSetAttribute(attn_mma_kernel,
                         cudaFuncAttributeMaxDynamicSharedMemorySize, ASMEM);

    // Prep
    {
        int n4 = MROWS * CDIM / 4;
        split_kernel<<<2048, 256>>>((const float4*)x, (uint2*)xh, (uint2*)xl, n4);
        transpose_split_kernel<<<dim3(THREEC / 32, CDIM / 32), dim3(32, 8)>>>(
            Wqkv, wqh, wql, CDIM, THREEC);
        transpose_split_kernel<<<dim3(CDIM / 32, CDIM / 32), dim3(32, 8)>>>(
            Wproj, wph, wpl, CDIM, CDIM);
    }

    // 1) QKV GEMM with fused split/remap epilogue
    gemm_mma_kernel<1><<<dim3(THREEC / 128, MROWS / 256), 256, GSMEM>>>(
        xh, xl, wqh, wql, bqkv, nullptr, MROWS, THREEC, CDIM);

    // 2) Tensor-core causal flash attention (128-query CTAs)
    attn_mma_kernel<<<dim3(TLEN / 128, NH, BSZ), 128, ASMEM>>>();

    // 3) Projection GEMM
    gemm_mma_kernel<0><<<dim3(CDIM / 128, MROWS / 256), 256, GSMEM>>>(
        ah, al, wph, wpl, bproj, out, MROWS, CDIM, CDIM);
}

// round 8
// speedup vs baseline: 1.1204x; 1.1204x over previous
#include <cuda_runtime.h>
#include <cuda_bf16.h>
#include <cstdint>
#include <cstddef>

// Problem constants
#define BSZ   4
#define TLEN  2048
#define CDIM  1024
#define NH    16
#define DH    64
#define MROWS (BSZ * TLEN)          // 8192
#define THREEC (3 * CDIM)           // 3072

// ---------------------------------------------------------------------------
// Scratch device globals
// ---------------------------------------------------------------------------
__device__ __nv_bfloat16 g_x_hi[(size_t)MROWS * CDIM];
__device__ __nv_bfloat16 g_x_lo[(size_t)MROWS * CDIM];
__device__ __nv_bfloat16 g_wqkv_hi[(size_t)THREEC * CDIM]; // W_qkv^T [N,K]
__device__ __nv_bfloat16 g_wqkv_lo[(size_t)THREEC * CDIM];
__device__ __nv_bfloat16 g_wp_hi[(size_t)CDIM * CDIM];     // W_proj^T [N,K]
__device__ __nv_bfloat16 g_wp_lo[(size_t)CDIM * CDIM];
// q,k: [b][h][t][d]; v transposed: [b][h][d][t]
__device__ __nv_bfloat16 g_qh[(size_t)MROWS * CDIM];
__device__ __nv_bfloat16 g_ql[(size_t)MROWS * CDIM];
__device__ __nv_bfloat16 g_kh[(size_t)MROWS * CDIM];
__device__ __nv_bfloat16 g_kl[(size_t)MROWS * CDIM];
__device__ __nv_bfloat16 g_vth[(size_t)MROWS * CDIM];
__device__ __nv_bfloat16 g_vtl[(size_t)MROWS * CDIM];
__device__ __nv_bfloat16 g_attn_hi[(size_t)MROWS * CDIM];  // [b*T+t][h*64+d]
__device__ __nv_bfloat16 g_attn_lo[(size_t)MROWS * CDIM];

// ---------------------------------------------------------------------------
// Helpers
// ---------------------------------------------------------------------------
__device__ __forceinline__ uint32_t smem_u32(const void* p) {
    uint32_t a;
    asm("{ .reg .u64 t; cvta.to.shared.u64 t, %1; cvt.u32.u64 %0, t; }"
        : "=r"(a) : "l"(p));
    return a;
}

__device__ __forceinline__ void cp_async16(uint32_t saddr, const void* gaddr) {
    asm volatile("cp.async.cg.shared.global [%0], [%1], 16;"
                 :: "r"(saddr), "l"(gaddr) : "memory");
}
#define CP_COMMIT() asm volatile("cp.async.commit_group;" ::: "memory")
#define CP_WAIT(n)  asm volatile("cp.async.wait_group %0;" :: "n"(n) : "memory")

__device__ __forceinline__ void mma_bf16(float* d, const uint32_t* a,
                                         uint32_t b0, uint32_t b1) {
    asm volatile(
        "mma.sync.aligned.m16n8k16.row.col.f32.bf16.bf16.f32 "
        "{%0,%1,%2,%3}, {%4,%5,%6,%7}, {%8,%9}, {%0,%1,%2,%3};"
        : "+f"(d[0]), "+f"(d[1]), "+f"(d[2]), "+f"(d[3])
        : "r"(a[0]), "r"(a[1]), "r"(a[2]), "r"(a[3]), "r"(b0), "r"(b1));
}

__device__ __forceinline__ void ldsm_x4(uint32_t* r, uint32_t addr) {
    asm volatile("ldmatrix.sync.aligned.m8n8.x4.shared.b16 {%0,%1,%2,%3}, [%4];"
                 : "=r"(r[0]), "=r"(r[1]), "=r"(r[2]), "=r"(r[3]) : "r"(addr));
}

// split two fp32 into packed bf16x2 hi and lo words
__device__ __forceinline__ void split2(float a, float b, uint32_t& hi, uint32_t& lo) {
    __nv_bfloat16 ha = __float2bfloat16(a), hb = __float2bfloat16(b);
    __nv_bfloat16 la = __float2bfloat16(a - __bfloat162float(ha));
    __nv_bfloat16 lb = __float2bfloat16(b - __bfloat162float(hb));
    hi = (uint32_t)__bfloat16_as_ushort(ha) | ((uint32_t)__bfloat16_as_ushort(hb) << 16);
    lo = (uint32_t)__bfloat16_as_ushort(la) | ((uint32_t)__bfloat16_as_ushort(lb) << 16);
}

// ---------------------------------------------------------------------------
// Prep kernels
// ---------------------------------------------------------------------------
__global__ void split_kernel(const float4* __restrict__ in,
                             uint2* __restrict__ hi, uint2* __restrict__ lo, int n4)
{
    for (int i = blockIdx.x * blockDim.x + threadIdx.x; i < n4; i += gridDim.x * blockDim.x) {
        float4 v = in[i];
        uint2 H, L;
        split2(v.x, v.y, H.x, L.x);
        split2(v.z, v.w, H.y, L.y);
        hi[i] = H;
        lo[i] = L;
    }
}

__global__ void transpose_split_kernel(const float* __restrict__ W,
                                       __nv_bfloat16* __restrict__ hi,
                                       __nv_bfloat16* __restrict__ lo,
                                       int K, int N)
{
    __shared__ float t[32][33];
    int n = blockIdx.x * 32 + threadIdx.x;
    int k = blockIdx.y * 32 + threadIdx.y;
    #pragma unroll
    for (int j = 0; j < 4; j++)
        t[threadIdx.y + j * 8][threadIdx.x] = W[(size_t)(k + j * 8) * N + n];
    __syncthreads();
    int k2 = blockIdx.y * 32 + threadIdx.x;
    int n2 = blockIdx.x * 32 + threadIdx.y;
    #pragma unroll
    for (int j = 0; j < 4; j++) {
        float v = t[threadIdx.x][threadIdx.y + j * 8];
        __nv_bfloat16 h = __float2bfloat16(v);
        hi[(size_t)(n2 + j * 8) * K + k2] = h;
        lo[(size_t)(n2 + j * 8) * K + k2] = __float2bfloat16(v - __bfloat162float(h));
    }
}

// ---------------------------------------------------------------------------
// mma.sync bf16x3 GEMM: C = (Ahi+Alo) @ (Bhi+Blo)^T + bias
// 128x128x32 CTA tile, 256 threads (8 warps, 2m x 4n), warp tile 64x32.
// Term-first MMA ordering (acc reuse distance 32).
// MODE 0: fp32 store to C.   MODE 1: QKV epilogue (split + head remap).
// ---------------------------------------------------------------------------
#define PAD    40
#define TBYTES (128 * PAD * 2)
#define STAGE  (4 * TBYTES)
#define GSMEM  (2 * STAGE)

template<int MODE>
__global__ __launch_bounds__(256) void gemm_mma_kernel(
    const __nv_bfloat16* __restrict__ Ahi,
    const __nv_bfloat16* __restrict__ Alo,
    const __nv_bfloat16* __restrict__ Bhi,
    const __nv_bfloat16* __restrict__ Blo,
    const float* __restrict__ bias,
    float* __restrict__ C,
    int M, int N, int K)
{
    extern __shared__ __align__(128) char smem[];
    const int tid  = threadIdx.x;
    const int wid  = tid >> 5;
    const int lane = tid & 31;
    const int wm   = wid & 1;
    const int wn   = wid >> 1;
    const int lr8  = lane & 7;
    const int g    = lane >> 3;
    const uint32_t sbase = smem_u32(smem);

    const int row0 = blockIdx.y * 128;
    const int col0 = blockIdx.x * 128;
    const int S = K >> 5;

    float acc[4][4][4] = {};

    const int lr  = tid >> 2;
    const int lc8 = (tid & 3) * 8;
    auto load_stage = [&](int s) {
        const uint32_t sb = sbase + (s & 1) * STAGE;
        const int k0 = s * 32;
        #pragma unroll
        for (int i = 0; i < 2; i++) {
            int r = lr + i * 64;
            uint32_t so = sb + (uint32_t)(r * (PAD * 2) + lc8 * 2);
            size_t ga = (size_t)(row0 + r) * K + k0 + lc8;
            size_t gb = (size_t)(col0 + r) * K + k0 + lc8;
            cp_async16(so + 0 * TBYTES, Ahi + ga);
            cp_async16(so + 1 * TBYTES, Alo + ga);
            cp_async16(so + 2 * TBYTES, Bhi + gb);
            cp_async16(so + 3 * TBYTES, Blo + gb);
        }
        CP_COMMIT();
    };

    load_stage(0);

    for (int s = 0; s < S; s++) {
        if (s + 1 < S) { load_stage(s + 1); CP_WAIT(1); } else { CP_WAIT(0); }
        __syncthreads();

        const uint32_t sA = sbase + (s & 1) * STAGE;
        const uint32_t sB = sA + 2 * TBYTES;

        #pragma unroll
        for (int kk = 0; kk < 2; kk++) {
            uint32_t ahi[4][4], alo[4][4], bhi[4][2], blo[4][2];
            #pragma unroll
            for (int mt = 0; mt < 4; mt++) {
                uint32_t a = sA + (uint32_t)(((wm * 64 + mt * 16 + (g & 1) * 8 + lr8) * PAD
                                              + kk * 16 + (g >> 1) * 8) * 2);
                ldsm_x4(ahi[mt], a);
                ldsm_x4(alo[mt], a + TBYTES);
            }
            #pragma unroll
            for (int np = 0; np < 2; np++) {
                uint32_t a = sB + (uint32_t)(((wn * 32 + np * 16 + (g >> 1) * 8 + lr8) * PAD
                                              + kk * 16 + (g & 1) * 8) * 2);
                uint32_t th[4], tl[4];
                ldsm_x4(th, a);
                ldsm_x4(tl, a + TBYTES);
                bhi[2 * np][0] = th[0]; bhi[2 * np][1] = th[1];
                bhi[2 * np + 1][0] = th[2]; bhi[2 * np + 1][1] = th[3];
                blo[2 * np][0] = tl[0]; blo[2 * np][1] = tl[1];
                blo[2 * np + 1][0] = tl[2]; blo[2 * np + 1][1] = tl[3];
            }
            // term-first: 32 independent MMAs per term
            #pragma unroll
            for (int mt = 0; mt < 4; mt++)
                #pragma unroll
                for (int nt = 0; nt < 4; nt++)
                    mma_bf16(acc[mt][nt], ahi[mt], bhi[nt][0], bhi[nt][1]);
            #pragma unroll
            for (int mt = 0; mt < 4; mt++)
                #pragma unroll
                for (int nt = 0; nt < 4; nt++)
                    mma_bf16(acc[mt][nt], ahi[mt], blo[nt][0], blo[nt][1]);
            #pragma unroll
            for (int mt = 0; mt < 4; mt++)
                #pragma unroll
                for (int nt = 0; nt < 4; nt++)
                    mma_bf16(acc[mt][nt], alo[mt], bhi[nt][0], bhi[nt][1]);
        }
        __syncthreads();
    }

    // ---- epilogue ----
    #pragma unroll
    for (int mt = 0; mt < 4; mt++) {
        #pragma unroll
        for (int nt = 0; nt < 4; nt++) {
            int r = row0 + wm * 64 + mt * 16 + (lane >> 2);
            int c = col0 + wn * 32 + nt * 8 + (lane & 3) * 2;
            float2 bv = *(const float2*)(bias + c);
            float v00 = acc[mt][nt][0] + bv.x, v01 = acc[mt][nt][1] + bv.y;
            float v10 = acc[mt][nt][2] + bv.x, v11 = acc[mt][nt][3] + bv.y;
            if (MODE == 0) {
                *(float2*)(C + (size_t)r * N + c)       = make_float2(v00, v01);
                *(float2*)(C + (size_t)(r + 8) * N + c) = make_float2(v10, v11);
            } else {
                const int sect = c >> 10;
                const int h = (c & 1023) >> 6;
                const int d = c & 63;
                #pragma unroll
                for (int half = 0; half < 2; half++) {
                    int rr = r + half * 8;
                    float a = half ? v10 : v00;
                    float bb = half ? v11 : v01;
                    int bidx = rr >> 11, t = rr & 2047;
                    if (sect == 0) { a *= 0.125f; bb *= 0.125f; }
                    uint32_t hiw, low;
                    if (sect == 2) {
                        __nv_bfloat16 ha = __float2bfloat16(a), hb = __float2bfloat16(bb);
                        __nv_bfloat16 la = __float2bfloat16(a - __bfloat162float(ha));
                        __nv_bfloat16 lb = __float2bfloat16(bb - __bfloat162float(hb));
                        size_t vb = ((size_t)(bidx * NH + h) * 64 + d) * TLEN + t;
                        g_vth[vb] = ha; g_vth[vb + TLEN] = hb;
                        g_vtl[vb] = la; g_vtl[vb + TLEN] = lb;
                    } else {
                        split2(a, bb, hiw, low);
                        size_t qb = ((size_t)(bidx * NH + h) * TLEN + t) * 64 + d;
                        if (sect == 0) {
                            *(uint32_t*)(g_qh + qb) = hiw;
                            *(uint32_t*)(g_ql + qb) = low;
                        } else {
                            *(uint32_t*)(g_kh + qb) = hiw;
                            *(uint32_t*)(g_kl + qb) = low;
                        }
                    }
                }
            }
        }
    }
}

// ---------------------------------------------------------------------------
// Flash attention, mma.sync bf16x3 + ldmatrix. 128 queries/CTA, 4 warps
// (32 q rows each), 64-key stages. Term-grouped MMA ordering.
// grid (T/128, H, B), block 128.
// ---------------------------------------------------------------------------
#define AST   72                      // bf16 elems per smem row (144B)
#define ATILE (64 * AST * 2)          // 9216 B
#define ASTAGE (4 * ATILE)            // 36864 B
#define ASMEM  (2 * ASTAGE)           // 73728 B

__global__ __launch_bounds__(128) void attn_mma_kernel()
{
    extern __shared__ __align__(128) char smem[];
    const int tid  = threadIdx.x;
    const int wid  = tid >> 5;        // 0..3
    const int lane = tid & 31;
    const int lr8  = lane & 7;
    const int g    = lane >> 3;
    const uint32_t sbase = smem_u32(smem);

    const int qt = (int)(gridDim.x - 1) - (int)blockIdx.x;   // reversed
    const size_t bh = (size_t)blockIdx.z * NH + blockIdx.y;

    // ---- stage Q tile (128 rows, hi/lo) into buffer 0, extract fragments ----
    {
        #pragma unroll
        for (int i = 0; i < 8; i++) {
            int f = i * 128 + tid;            // 0..1023
            int r = f >> 3, ch = f & 7;
            uint32_t so = sbase + (uint32_t)(r * 144 + ch * 16);
            size_t ga = ((bh * TLEN + qt * 128 + r) << 6) + ch * 8;
            cp_async16(so,         g_qh + ga);
            cp_async16(so + 18432, g_ql + ga);
        }
        CP_COMMIT();
        CP_WAIT(0);
        __syncthreads();
    }

    uint32_t qhi[2][4][4], qlo[2][4][4];
    #pragma unroll
    for (int mt = 0; mt < 2; mt++)
        #pragma unroll
        for (int ks = 0; ks < 4; ks++) {
            uint32_t a = sbase + (uint32_t)(((wid * 32 + mt * 16 + (g & 1) * 8 + lr8) * AST
                                             + ks * 16 + (g >> 1) * 8) * 2);
            ldsm_x4(qhi[mt][ks], a);
            ldsm_x4(qlo[mt][ks], a + 18432);
        }
    __syncthreads();   // done reading buffer 0 as Q

    float o[2][8][4] = {};
    float m[2][2] = {{-1e30f, -1e30f}, {-1e30f, -1e30f}};
    float l[2][2] = {};

    auto load_kv = [&](int kt) {
        const uint32_t sb = sbase + (kt & 1) * ASTAGE;
        #pragma unroll
        for (int i = 0; i < 4; i++) {
            int f = i * 128 + tid;
            int r = f >> 3, ch = f & 7;
            uint32_t so = sb + (uint32_t)(r * 144 + ch * 16);
            size_t gk = ((bh * TLEN + kt * 64 + r) << 6) + ch * 8;
            size_t gv = (bh * 64 + r) * TLEN + kt * 64 + ch * 8;
            cp_async16(so + 0 * ATILE, g_kh + gk);
            cp_async16(so + 1 * ATILE, g_kl + gk);
            cp_async16(so + 2 * ATILE, g_vth + gv);
            cp_async16(so + 3 * ATILE, g_vtl + gv);
        }
        CP_COMMIT();
    };

    const int nkt = 2 * qt + 2;
    load_kv(0);

    for (int kt = 0; kt < nkt; kt++) {
        if (kt + 1 < nkt) { load_kv(kt + 1); CP_WAIT(1); } else { CP_WAIT(0); }
        __syncthreads();

        const uint32_t sbK = sbase + (kt & 1) * ASTAGE;
        const uint32_t sbV = sbK + 2 * ATILE;

        // ---- S = Q K^T (term-grouped per np) ----
        float s[2][8][4] = {};
        #pragma unroll
        for (int ks = 0; ks < 4; ks++) {
            #pragma unroll
            for (int np = 0; np < 4; np++) {
                uint32_t a = sbK + (uint32_t)(((np * 16 + (g >> 1) * 8 + lr8) * AST
                                               + ks * 16 + (g & 1) * 8) * 2);
                uint32_t kh4[4], kl4[4];
                ldsm_x4(kh4, a);
                ldsm_x4(kl4, a + ATILE);
                // term hh (4 independent)
                mma_bf16(s[0][2 * np],     qhi[0][ks], kh4[0], kh4[1]);
                mma_bf16(s[1][2 * np],     qhi[1][ks], kh4[0], kh4[1]);
                mma_bf16(s[0][2 * np + 1], qhi[0][ks], kh4[2], kh4[3]);
                mma_bf16(s[1][2 * np + 1], qhi[1][ks], kh4[2], kh4[3]);
                // term hl
                mma_bf16(s[0][2 * np],     qhi[0][ks], kl4[0], kl4[1]);
                mma_bf16(s[1][2 * np],     qhi[1][ks], kl4[0], kl4[1]);
                mma_bf16(s[0][2 * np + 1], qhi[0][ks], kl4[2], kl4[3]);
                mma_bf16(s[1][2 * np + 1], qhi[1][ks], kl4[2], kl4[3]);
                // term lh
                mma_bf16(s[0][2 * np],     qlo[0][ks], kh4[0], kh4[1]);
                mma_bf16(s[1][2 * np],     qlo[1][ks], kh4[0], kh4[1]);
                mma_bf16(s[0][2 * np + 1], qlo[0][ks], kh4[2], kh4[3]);
                mma_bf16(s[1][2 * np + 1], qlo[1][ks], kh4[2], kh4[3]);
            }
        }

        // ---- causal mask on diagonal tiles ----
        if (kt >= 2 * qt) {
            #pragma unroll
            for (int mt = 0; mt < 2; mt++) {
                int qr = qt * 128 + wid * 32 + mt * 16 + (lane >> 2);
                #pragma unroll
                for (int nt = 0; nt < 8; nt++) {
                    int kc = kt * 64 + nt * 8 + (lane & 3) * 2;
                    if (kc > qr)         s[mt][nt][0] = -1e30f;
                    if (kc + 1 > qr)     s[mt][nt][1] = -1e30f;
                    if (kc > qr + 8)     s[mt][nt][2] = -1e30f;
                    if (kc + 1 > qr + 8) s[mt][nt][3] = -1e30f;
                }
            }
        }

        // ---- online softmax ----
        #pragma unroll
        for (int mt = 0; mt < 2; mt++) {
            float mx0 = -1e30f, mx1 = -1e30f;
            #pragma unroll
            for (int nt = 0; nt < 8; nt++) {
                mx0 = fmaxf(mx0, fmaxf(s[mt][nt][0], s[mt][nt][1]));
                mx1 = fmaxf(mx1, fmaxf(s[mt][nt][2], s[mt][nt][3]));
            }
            mx0 = fmaxf(mx0, __shfl_xor_sync(0xffffffff, mx0, 1));
            mx0 = fmaxf(mx0, __shfl_xor_sync(0xffffffff, mx0, 2));
            mx1 = fmaxf(mx1, __shfl_xor_sync(0xffffffff, mx1, 1));
            mx1 = fmaxf(mx1, __shfl_xor_sync(0xffffffff, mx1, 2));

            float mn0 = fmaxf(m[mt][0], mx0), mn1 = fmaxf(m[mt][1], mx1);
            float a0 = __expf(m[mt][0] - mn0), a1 = __expf(m[mt][1] - mn1);
            m[mt][0] = mn0; m[mt][1] = mn1;
            #pragma unroll
            for (int nt = 0; nt < 8; nt++) {
                o[mt][nt][0] *= a0; o[mt][nt][1] *= a0;
                o[mt][nt][2] *= a1; o[mt][nt][3] *= a1;
            }

            float sum0 = 0.f, sum1 = 0.f;
            #pragma unroll
            for (int nt = 0; nt < 8; nt++) {
                s[mt][nt][0] = __expf(s[mt][nt][0] - mn0);
                s[mt][nt][1] = __expf(s[mt][nt][1] - mn0);
                s[mt][nt][2] = __expf(s[mt][nt][2] - mn1);
                s[mt][nt][3] = __expf(s[mt][nt][3] - mn1);
                sum0 += s[mt][nt][0] + s[mt][nt][1];
                sum1 += s[mt][nt][2] + s[mt][nt][3];
            }
            sum0 += __shfl_xor_sync(0xffffffff, sum0, 1);
            sum0 += __shfl_xor_sync(0xffffffff, sum0, 2);
            sum1 += __shfl_xor_sync(0xffffffff, sum1, 1);
            sum1 += __shfl_xor_sync(0xffffffff, sum1, 2);
            l[mt][0] = l[mt][0] * a0 + sum0;
            l[mt][1] = l[mt][1] * a1 + sum1;
        }

        uint32_t phi[2][4][4], plo[2][4][4];
        #pragma unroll
        for (int mt = 0; mt < 2; mt++)
            #pragma unroll
            for (int ks = 0; ks < 4; ks++) {
                split2(s[mt][2 * ks][0],     s[mt][2 * ks][1],     phi[mt][ks][0], plo[mt][ks][0]);
                split2(s[mt][2 * ks][2],     s[mt][2 * ks][3],     phi[mt][ks][1], plo[mt][ks][1]);
                split2(s[mt][2 * ks + 1][0], s[mt][2 * ks + 1][1], phi[mt][ks][2], plo[mt][ks][2]);
                split2(s[mt][2 * ks + 1][2], s[mt][2 * ks + 1][3], phi[mt][ks][3], plo[mt][ks][3]);
            }

        // ---- O += P V (term-grouped per np) ----
        #pragma unroll
        for (int ks = 0; ks < 4; ks++) {
            #pragma unroll
            for (int np = 0; np < 4; np++) {
                uint32_t a = sbV + (uint32_t)(((np * 16 + (g >> 1) * 8 + lr8) * AST
                                               + ks * 16 + (g & 1) * 8) * 2);
                uint32_t vh4[4], vl4[4];
                ldsm_x4(vh4, a);
                ldsm_x4(vl4, a + ATILE);
                // term hh
                mma_bf16(o[0][2 * np],     phi[0][ks], vh4[0], vh4[1]);
                mma_bf16(o[1][2 * np],     phi[1][ks], vh4[0], vh4[1]);
                mma_bf16(o[0][2 * np + 1], phi[0][ks], vh4[2], vh4[3]);
                mma_bf16(o[1][2 * np + 1], phi[1][ks], vh4[2], vh4[3]);
                // term lh (plo * vhi)
                mma_bf16(o[0][2 * np],     plo[0][ks], vh4[0], vh4[1]);
                mma_bf16(o[1][2 * np],     plo[1][ks], vh4[0], vh4[1]);
                mma_bf16(o[0][2 * np + 1], plo[0][ks], vh4[2], vh4[3]);
                mma_bf16(o[1][2 * np + 1], plo[1][ks], vh4[2], vh4[3]);
                // term hl (phi * vlo)
                mma_bf16(o[0][2 * np],     phi[0][ks], vl4[0], vl4[1]);
                mma_bf16(o[1][2 * np],     phi[1][ks], vl4[0], vl4[1]);
                mma_bf16(o[0][2 * np + 1], phi[0][ks], vl4[2], vl4[3]);
                mma_bf16(o[1][2 * np + 1], phi[1][ks], vl4[2], vl4[3]);
            }
        }
        __syncthreads();
    }

    // ---- finalize + store hi/lo split ----
    #pragma unroll
    for (int mt = 0; mt < 2; mt++) {
        const float inv0 = 1.0f / l[mt][0];
        const float inv1 = 1.0f / l[mt][1];
        const int t0 = qt * 128 + wid * 32 + mt * 16 + (lane >> 2);
        const size_t row0 = (size_t)blockIdx.z * TLEN + t0;
        const int colb = blockIdx.y * 64 + (lane & 3) * 2;
        #pragma unroll
        for (int dn = 0; dn < 8; dn++) {
            int col = colb + dn * 8;
            uint32_t hiw, low;
            split2(o[mt][dn][0] * inv0, o[mt][dn][1] * inv0, hiw, low);
            *(uint32_t*)(g_attn_hi + row0 * CDIM + col) = hiw;
            *(uint32_t*)(g_attn_lo + row0 * CDIM + col) = low;
            split2(o[mt][dn][2] * inv1, o[mt][dn][3] * inv1, hiw, low);
            *(uint32_t*)(g_attn_hi + (row0 + 8) * CDIM + col) = hiw;
            *(uint32_t*)(g_attn_lo + (row0 + 8) * CDIM + col) = low;
        }
    }
}

// ---------------------------------------------------------------------------
// kernel_launch
// ---------------------------------------------------------------------------
extern "C" void kernel_launch(void* const* d_in, const int* in_sizes, int n_in,
                              void* d_out, int out_size)
{
    const float* x     = (const float*)d_in[0];
    const float* Wqkv  = (const float*)d_in[1];
    const float* bqkv  = (const float*)d_in[2];
    const float* Wproj = (const float*)d_in[3];
    const float* bproj = (const float*)d_in[4];
    float* out = (float*)d_out;

    __nv_bfloat16 *xh, *xl, *wqh, *wql, *wph, *wpl, *ah, *al;
    cudaGetSymbolAddress((void**)&xh, g_x_hi);
    cudaGetSymbolAddress((void**)&xl, g_x_lo);
    cudaGetSymbolAddress((void**)&wqh, g_wqkv_hi);
    cudaGetSymbolAddress((void**)&wql, g_wqkv_lo);
    cudaGetSymbolAddress((void**)&wph, g_wp_hi);
    cudaGetSymbolAddress((void**)&wpl, g_wp_lo);
    cudaGetSymbolAddress((void**)&ah, g_attn_hi);
    cudaGetSymbolAddress((void**)&al, g_attn_lo);

    cudaFuncSetAttribute(gemm_mma_kernel<0>,
                         cudaFuncAttributeMaxDynamicSharedMemorySize, GSMEM);
    cudaFuncSetAttribute(gemm_mma_kernel<1>,
                         cudaFuncAttributeMaxDynamicSharedMemorySize, GSMEM);
    cudaFuncSetAttribute(attn_mma_kernel,
                         cudaFuncAttributeMaxDynamicSharedMemorySize, ASMEM);

    // Prep
    {
        int n4 = MROWS * CDIM / 4;
        split_kernel<<<2048, 256>>>((const float4*)x, (uint2*)xh, (uint2*)xl, n4);
        transpose_split_kernel<<<dim3(THREEC / 32, CDIM / 32), dim3(32, 8)>>>(
            Wqkv, wqh, wql, CDIM, THREEC);
        transpose_split_kernel<<<dim3(CDIM / 32, CDIM / 32), dim3(32, 8)>>>(
            Wproj, wph, wpl, CDIM, CDIM);
    }

    // 1) QKV GEMM with fused split/remap epilogue
    gemm_mma_kernel<1><<<dim3(THREEC / 128, MROWS / 128), 256, GSMEM>>>(
        xh, xl, wqh, wql, bqkv, nullptr, MROWS, THREEC, CDIM);

    // 2) Tensor-core causal flash attention (128-query CTAs)
    attn_mma_kernel<<<dim3(TLEN / 128, NH, BSZ), 128, ASMEM>>>();

    // 3) Projection GEMM
    gemm_mma_kernel<0><<<dim3(CDIM / 128, MROWS / 128), 256, GSMEM>>>(
        ah, al, wph, wpl, bproj, out, MROWS, CDIM, CDIM);
}